// round 5
// baseline (speedup 1.0000x reference)
#include <cuda_runtime.h>
#include <math.h>

#define SS 7
#define NB 49          // boxes per image
#define NC 20          // classes
#define NBATCH 4096
#define DD 30          // channels per cell

// ---------------- scratch (device globals; no allocation) ----------------
__device__ int    g_records[NBATCH * NB];       // packed per-pred record
__device__ int    g_nvalid[NC * NBATCH];        // per class, per image valid count
__device__ int    g_ntp[NC * NBATCH];           // per class, per image tp count
__device__ int    g_offv[NC * NBATCH];          // exclusive scans over images
__device__ int    g_offt[NC * NBATCH];
__device__ int    g_gt[NC];                     // per-class GT counts
__device__ double g_ap[NC];                     // per-class AP accumulators

// ---------------- helpers ----------------
__device__ __forceinline__ float sigm(float x) { return 1.0f / (1.0f + expf(-x)); }

__device__ __forceinline__ float iou4(const float* a, const float* b) {
    float lx = fmaxf(a[0], b[0]), ly = fmaxf(a[1], b[1]);
    float rx = fminf(a[2], b[2]), ry = fminf(a[3], b[3]);
    float w = fmaxf(rx - lx, 0.0f), h = fmaxf(ry - ly, 0.0f);
    float inter = w * h;
    float aa = (a[2] - a[0]) * (a[3] - a[1]);
    float ab = (b[2] - b[0]) * (b[3] - b[1]);
    return inter / (aa + ab - inter);
}

__device__ __forceinline__ void decode_box(float x, float y, float w, float h,
                                           int iy, int jx, float* out) {
    const float gw = 448.0f / 7.0f;  // 64
    float cx = (x + (float)jx) * gw;
    float cy = (y + (float)iy) * gw;
    float W = w * 448.0f, H = h * 448.0f;
    out[0] = cx - W * 0.5f;
    out[1] = cy - H * 0.5f;
    out[2] = cx + W * 0.5f;
    out[3] = cy + H * 0.5f;
}

// ---------------- kernel 0: init ----------------
__global__ void k_init() {
    int t = threadIdx.x;
    if (t < NC) { g_gt[t] = 0; g_ap[t] = 0.0; }
}

// ---------------- kernel 1: per-image pipeline ----------------
__global__ __launch_bounds__(64) void k_per_image(const float* __restrict__ tgt,
                                                  const float* __restrict__ outp) {
    int img = blockIdx.x;
    int t = threadIdx.x;

    __shared__ float uconf[NB];
    __shared__ float ub[NB][4];
    __shared__ int   ucls[NB];
    __shared__ float gb[NB][4];
    __shared__ int   gcls[NB];
    __shared__ unsigned char gval[NB];
    __shared__ int   order[NB];
    __shared__ float sconf[NB];
    __shared__ float sb[NB][4];
    __shared__ int   scls[NB];
    __shared__ unsigned long long sup[NB];
    __shared__ float smx[NB];
    __shared__ int   sbest[NB];
    __shared__ unsigned long long sh_valid, sh_tp;

    // ---- per-cell decode ----
    if (t < NB) {
        int iy = t / SS, jx = t % SS;
        const float* o = outp + ((size_t)img * NB + t) * DD;
        const float* g = tgt + ((size_t)img * NB + t) * DD;

        // prediction: responsible box (argmax of 2 confs, first on tie)
        float c0 = sigm(o[4]);
        float c1 = sigm(o[9]);
        int resp = (c1 > c0) ? 1 : 0;
        float conf = (resp ? c1 : c0);
        const float* oc = o + resp * 5;
        float px = sigm(oc[0]), py = sigm(oc[1]), pw = sigm(oc[2]), ph = sigm(oc[3]);
        decode_box(px, py, pw, ph, iy, jx, ub[t]);
        uconf[t] = conf;
        // pred class argmax (sigmoid is monotone -> argmax of raw)
        float bm = o[10]; int bi = 0;
        #pragma unroll
        for (int k = 1; k < NC; k++) { float v = o[10 + k]; if (v > bm) { bm = v; bi = k; } }
        ucls[t] = bi;

        // ground truth
        float gconf = g[4];
        gval[t] = (gconf > 0.5f) ? 1 : 0;
        decode_box(g[0], g[1], g[2], g[3], iy, jx, gb[t]);
        float gm = g[10]; int gi = 0;
        #pragma unroll
        for (int k = 1; k < NC; k++) { float v = g[10 + k]; if (v > gm) { gm = v; gi = k; } }
        gcls[t] = gi;
    }
    __syncthreads();

    // ---- stable sort by conf desc (rank counting) ----
    if (t < NB) {
        float ci = uconf[t];
        int r = 0;
        for (int j = 0; j < NB; j++) {
            float cj = uconf[j];
            r += (cj > ci) || (cj == ci && j < t);
        }
        order[r] = t;
    }
    __syncthreads();
    if (t < NB) {
        int i = order[t];
        sconf[t] = uconf[i];
        scls[t] = ucls[i];
        sb[t][0] = ub[i][0]; sb[t][1] = ub[i][1]; sb[t][2] = ub[i][2]; sb[t][3] = ub[i][3];
    }
    __syncthreads();

    // ---- NMS suppression rows + best-GT IoU (parallel over sorted preds) ----
    if (t < NB) {
        unsigned long long m = 0ull;
        int c = scls[t];
        for (int j = 0; j < NB; j++) {
            if (scls[j] == c && iou4(sb[t], sb[j]) > 0.5f) m |= (1ull << j);
        }
        sup[t] = m;

        float mx = -1.0f; int best = 0;
        for (int gidx = 0; gidx < NB; gidx++) {
            if (gval[gidx] && gcls[gidx] == c) {
                float v = iou4(sb[t], gb[gidx]);
                if (v > mx) { mx = v; best = gidx; }
            }
        }
        smx[t] = mx; sbest[t] = best;
    }
    __syncthreads();

    // ---- serial greedy NMS + TP matching (thread 0) ----
    if (t == 0) {
        unsigned long long suppressed = 0ull, keep = 0ull;
        for (int i = 0; i < NB; i++) {
            if (!((suppressed >> i) & 1ull)) {
                keep |= (1ull << i);
                suppressed |= sup[i] & ~((2ull << i) - 1ull);
            }
        }
        unsigned long long valid = 0ull;
        for (int i = 0; i < NB; i++)
            if (((keep >> i) & 1ull) && sconf[i] > 0.5f) valid |= (1ull << i);

        unsigned long long matched = 0ull, tpm = 0ull;
        for (int i = 0; i < NB; i++) {
            if (((valid >> i) & 1ull) && smx[i] > 0.5f && !((matched >> sbest[i]) & 1ull)) {
                matched |= (1ull << sbest[i]);
                tpm |= (1ull << i);
            }
        }
        sh_valid = valid; sh_tp = tpm;
    }
    __syncthreads();

    unsigned long long vm = sh_valid, tm = sh_tp;

    // ---- per-pred records (parallel local rank / inclusive tp count) ----
    if (t < NB) {
        int rec = 0;
        if ((vm >> t) & 1ull) {
            int c = scls[t];
            int rank = 0, tpc = 0;
            for (int j = 0; j <= t; j++) {
                if (((vm >> j) & 1ull) && scls[j] == c) {
                    if (j < t) rank++;
                    tpc += (int)((tm >> j) & 1ull);
                }
            }
            int tp = (int)((tm >> t) & 1ull);
            rec = 0x40000000 | c | (rank << 8) | (tpc << 16) | (tp << 24);
        }
        g_records[img * NB + t] = rec;
    }

    // ---- per-class per-image counts + GT counts ----
    if (t < NC) {
        int nv = 0, nt = 0, ng = 0;
        for (int j = 0; j < NB; j++) {
            if (((vm >> j) & 1ull) && scls[j] == t) {
                nv++;
                nt += (int)((tm >> j) & 1ull);
            }
            if (gval[j] && gcls[j] == t) ng++;
        }
        g_nvalid[t * NBATCH + img] = nv;
        g_ntp[t * NBATCH + img] = nt;
        if (ng) atomicAdd(&g_gt[t], ng);
    }
}

// ---------------- kernel 2: exclusive scan over images per (class, kind) ----------------
__global__ __launch_bounds__(1024) void k_scan() {
    __shared__ int sh[1024];
    int bx = blockIdx.x;            // 0..39
    const int* in = (bx < NC) ? (g_nvalid + bx * NBATCH) : (g_ntp + (bx - NC) * NBATCH);
    int* out = (bx < NC) ? (g_offv + bx * NBATCH) : (g_offt + (bx - NC) * NBATCH);
    int t = threadIdx.x;            // 1024 threads x 4 elems = 4096

    int v0 = in[t * 4 + 0], v1 = in[t * 4 + 1], v2 = in[t * 4 + 2], v3 = in[t * 4 + 3];
    int e1 = v0, e2 = v0 + v1, e3 = v0 + v1 + v2;
    int sum = e3 + v3;
    sh[t] = sum;
    __syncthreads();
    // inclusive Hillis-Steele
    for (int off = 1; off < 1024; off <<= 1) {
        int x = (t >= off) ? sh[t - off] : 0;
        __syncthreads();
        sh[t] += x;
        __syncthreads();
    }
    int prefix = (t > 0) ? sh[t - 1] : 0;
    out[t * 4 + 0] = prefix;
    out[t * 4 + 1] = prefix + e1;
    out[t * 4 + 2] = prefix + e2;
    out[t * 4 + 3] = prefix + e3;
}

// ---------------- kernel 3: AP term accumulation ----------------
__global__ void k_ap() {
    int idx = blockIdx.x * blockDim.x + threadIdx.x;
    if (idx >= NBATCH * NB) return;
    int rec = g_records[idx];
    if (!(rec & 0x40000000)) return;
    int tp = (rec >> 24) & 1;
    if (!tp) return;

    int c = rec & 0xFF;
    int rank = (rec >> 8) & 0xFF;
    int tpc_loc = (rec >> 16) & 0xFF;
    int img = idx / NB;

    int j = g_offv[c * NBATCH + img] + rank + 1;      // 1-based global valid rank
    int tpc = g_offt[c * NBATCH + img] + tpc_loc;     // inclusive cumulative TP

    float pj = (float)tpc / ((float)j + 1e-6f);
    float pprev;
    if (j == 1) {
        pprev = (idx == 0) ? 1.0f : 0.0f;             // only global position 0 sees prepended p=1
    } else {
        pprev = (float)(tpc - 1) / ((float)(j - 1) + 1e-6f);
    }
    float gt = (float)g_gt[c];
    double term = (double)(pj + pprev) * 0.5 / (double)(gt + 1e-6f);
    atomicAdd(&g_ap[c], term);
}

// ---------------- kernel 4: finalize mAP ----------------
__global__ void k_final(float* out) {
    if (threadIdx.x == 0) {
        double s = 0.0; int n = 0;
        for (int c = 0; c < NC; c++) {
            if (g_gt[c] > 0) { s += g_ap[c]; n++; }
        }
        double nh = (n > 0) ? (double)n : 1.0;
        out[0] = (float)(s / nh);
    }
}

// ---------------- launcher ----------------
extern "C" void kernel_launch(void* const* d_in, const int* in_sizes, int n_in,
                              void* d_out, int out_size) {
    const float* tgt = (const float*)d_in[0];
    const float* outp = (const float*)d_in[1];
    float* out = (float*)d_out;

    k_init<<<1, 32>>>();
    k_per_image<<<NBATCH, 64>>>(tgt, outp);
    k_scan<<<40, 1024>>>();
    k_ap<<<(NBATCH * NB + 255) / 256, 256>>>();
    k_final<<<1, 32>>>(out);
}

// round 6
// speedup vs baseline: 1.1022x; 1.1022x over previous
#include <cuda_runtime.h>
#include <math.h>

#define SS 7
#define NB 49          // boxes per image
#define NC 20          // classes
#define NBATCH 4096
#define DD 30          // channels per cell

// ---------------- scratch (device globals; no allocation) ----------------
__device__ __align__(256) int    g_records[NBATCH * NB];   // packed per-pred record
__device__ __align__(256) int    g_nvalid[NC * NBATCH];    // per class, per image valid count
__device__ __align__(256) int    g_ntp[NC * NBATCH];       // per class, per image tp count
__device__ __align__(256) int    g_offv[NC * NBATCH];      // exclusive scans over images
__device__ __align__(256) int    g_offt[NC * NBATCH];
__device__ int    g_gt[NC];                                // per-class GT counts
__device__ double g_ap[NC];                                // per-class AP accumulators

// ---------------- helpers ----------------
__device__ __forceinline__ float sigm(float x) { return 1.0f / (1.0f + expf(-x)); }

__device__ __forceinline__ float iou_a(float ax0, float ay0, float ax1, float ay1, float aar,
                                       const float* b, float bar) {
    float lx = fmaxf(ax0, b[0]), ly = fmaxf(ay0, b[1]);
    float rx = fminf(ax1, b[2]), ry = fminf(ay1, b[3]);
    float w = fmaxf(rx - lx, 0.0f), h = fmaxf(ry - ly, 0.0f);
    float inter = w * h;
    return inter / (aar + bar - inter);
}

// ---------------- kernel 0: init ----------------
__global__ void k_init() {
    int t = threadIdx.x;
    if (t < NC) { g_gt[t] = 0; g_ap[t] = 0.0; }
}

// ---------------- kernel 1: per-image pipeline ----------------
__global__ __launch_bounds__(64) void k_per_image(const float* __restrict__ tgt,
                                                  const float* __restrict__ outp) {
    int img = blockIdx.x;
    int t = threadIdx.x;

    // staging buffer for one image tensor (49*30 floats = 5880 B), coalesced fill.
    // After the GT decode it is dead; sup/smx/sbest alias into it.
    __shared__ __align__(16) float stage[1470];
    __shared__ float uconf[NB];
    __shared__ float sconf[NB];
    __shared__ float sb[NB][4];
    __shared__ float sarea[NB];
    __shared__ int   scls[NB];
    __shared__ float gb[NB][4];
    __shared__ float garea[NB];
    __shared__ int   gcls[NB];
    __shared__ unsigned char gval[NB];
    __shared__ unsigned long long sh_valid, sh_tp;

    unsigned long long* sup = (unsigned long long*)stage;   // 49*8 = 392 B
    float* smx  = stage + 98;                               // +392 B
    int*   sbest = (int*)(stage + 98 + 49);                 // +588 B  (<= 5880 B total)

    // ---- stage prediction tensor (coalesced float2) ----
    {
        const float2* src = reinterpret_cast<const float2*>(outp) + (size_t)img * 735;
        float2* dst = reinterpret_cast<float2*>(stage);
        #pragma unroll
        for (int i = t; i < 735; i += 64) dst[i] = src[i];
    }
    __syncthreads();

    float bx0 = 0.f, by0 = 0.f, bx1 = 0.f, by1 = 0.f, conf = 0.f;
    int cls = 0;
    if (t < NB) {
        const float* o = stage + t * DD;
        float c0 = sigm(o[4]);
        float c1 = sigm(o[9]);
        int resp = (c1 > c0) ? 1 : 0;
        conf = resp ? c1 : c0;
        const float* oc = o + resp * 5;
        float px = sigm(oc[0]), py = sigm(oc[1]), pw = sigm(oc[2]), ph = sigm(oc[3]);
        int iy = t / SS, jx = t % SS;
        float cx = (px + (float)jx) * 64.0f;
        float cy = (py + (float)iy) * 64.0f;
        float W = pw * 448.0f, H = ph * 448.0f;
        bx0 = cx - W * 0.5f; by0 = cy - H * 0.5f;
        bx1 = cx + W * 0.5f; by1 = cy + H * 0.5f;
        uconf[t] = conf;
        // class argmax (sigmoid monotone -> argmax of raw logits)
        float bm = o[10]; int bi = 0;
        #pragma unroll
        for (int k = 1; k < NC; k++) { float v = o[10 + k]; if (v > bm) { bm = v; bi = k; } }
        cls = bi;
    }
    __syncthreads();

    // ---- stable sort by conf desc: compute rank, scatter directly ----
    if (t < NB) {
        int r = 0;
        float ci = conf;
        for (int j = 0; j < NB; j++) {
            float cj = uconf[j];
            r += (cj > ci) || (cj == ci && j < t);
        }
        sconf[r] = ci;
        scls[r] = cls;
        sb[r][0] = bx0; sb[r][1] = by0; sb[r][2] = bx1; sb[r][3] = by1;
        sarea[r] = (bx1 - bx0) * (by1 - by0);
    }
    __syncthreads();

    // ---- stage target tensor (reuse staging buffer) ----
    {
        const float2* src = reinterpret_cast<const float2*>(tgt) + (size_t)img * 735;
        float2* dst = reinterpret_cast<float2*>(stage);
        #pragma unroll
        for (int i = t; i < 735; i += 64) dst[i] = src[i];
    }
    __syncthreads();

    if (t < NB) {
        const float* g = stage + t * DD;
        gval[t] = (g[4] > 0.5f) ? 1 : 0;
        int iy = t / SS, jx = t % SS;
        float cx = (g[0] + (float)jx) * 64.0f;
        float cy = (g[1] + (float)iy) * 64.0f;
        float W = g[2] * 448.0f, H = g[3] * 448.0f;
        float x0 = cx - W * 0.5f, y0 = cy - H * 0.5f;
        float x1 = cx + W * 0.5f, y1 = cy + H * 0.5f;
        gb[t][0] = x0; gb[t][1] = y0; gb[t][2] = x1; gb[t][3] = y1;
        garea[t] = (x1 - x0) * (y1 - y0);
        float gm = g[10]; int gi = 0;
        #pragma unroll
        for (int k = 1; k < NC; k++) { float v = g[10 + k]; if (v > gm) { gm = v; gi = k; } }
        gcls[t] = gi;
    }
    __syncthreads();   // stage dead from here; sup/smx/sbest may now be written

    // ---- NMS suppression rows + best-GT IoU (parallel over sorted preds) ----
    if (t < NB) {
        float ax0 = sb[t][0], ay0 = sb[t][1], ax1 = sb[t][2], ay1 = sb[t][3];
        float aar = sarea[t];
        int c = scls[t];
        unsigned long long m = 0ull;
        for (int j = 0; j < NB; j++) {
            if (scls[j] == c && iou_a(ax0, ay0, ax1, ay1, aar, sb[j], sarea[j]) > 0.5f)
                m |= (1ull << j);
        }
        sup[t] = m;

        float mx = -1.0f; int best = 0;
        for (int gidx = 0; gidx < NB; gidx++) {
            if (gval[gidx] && gcls[gidx] == c) {
                float v = iou_a(ax0, ay0, ax1, ay1, aar, gb[gidx], garea[gidx]);
                if (v > mx) { mx = v; best = gidx; }
            }
        }
        smx[t] = mx; sbest[t] = best;
    }
    __syncthreads();

    // ---- serial greedy NMS + TP matching (thread 0) ----
    if (t == 0) {
        unsigned long long suppressed = 0ull, keep = 0ull;
        for (int i = 0; i < NB; i++) {
            if (!((suppressed >> i) & 1ull)) {
                keep |= (1ull << i);
                suppressed |= sup[i] & ~((2ull << i) - 1ull);
            }
        }
        unsigned long long valid = 0ull;
        for (int i = 0; i < NB; i++)
            if (((keep >> i) & 1ull) && sconf[i] > 0.5f) valid |= (1ull << i);

        unsigned long long matched = 0ull, tpm = 0ull;
        for (int i = 0; i < NB; i++) {
            if (((valid >> i) & 1ull) && smx[i] > 0.5f && !((matched >> sbest[i]) & 1ull)) {
                matched |= (1ull << sbest[i]);
                tpm |= (1ull << i);
            }
        }
        sh_valid = valid; sh_tp = tpm;
    }
    __syncthreads();

    unsigned long long vm = sh_valid, tm = sh_tp;

    // ---- per-pred records (parallel local rank / inclusive tp count) ----
    if (t < NB) {
        int rec = 0;
        if ((vm >> t) & 1ull) {
            int c = scls[t];
            int rank = 0, tpc = 0;
            for (int j = 0; j <= t; j++) {
                if (((vm >> j) & 1ull) && scls[j] == c) {
                    if (j < t) rank++;
                    tpc += (int)((tm >> j) & 1ull);
                }
            }
            int tp = (int)((tm >> t) & 1ull);
            rec = 0x40000000 | c | (rank << 8) | (tpc << 16) | (tp << 24);
        }
        g_records[img * NB + t] = rec;
    }

    // ---- per-class per-image counts + GT counts ----
    if (t < NC) {
        int nv = 0, nt = 0, ng = 0;
        for (int j = 0; j < NB; j++) {
            if (((vm >> j) & 1ull) && scls[j] == t) {
                nv++;
                nt += (int)((tm >> j) & 1ull);
            }
            if (gval[j] && gcls[j] == t) ng++;
        }
        g_nvalid[t * NBATCH + img] = nv;
        g_ntp[t * NBATCH + img] = nt;
        if (ng) atomicAdd(&g_gt[t], ng);
    }
}

// ---------------- kernel 2: exclusive scan over images per (class, kind) ----------------
__global__ __launch_bounds__(1024) void k_scan() {
    __shared__ int wsum[32];
    int bx = blockIdx.x;            // 0..39
    int t = threadIdx.x;            // 1024 threads x 4 elems = 4096
    const int* in = (bx < NC) ? (g_nvalid + bx * NBATCH) : (g_ntp + (bx - NC) * NBATCH);
    int* out = (bx < NC) ? (g_offv + bx * NBATCH) : (g_offt + (bx - NC) * NBATCH);

    int4 v = reinterpret_cast<const int4*>(in)[t];
    int e1 = v.x, e2 = e1 + v.y, e3 = e2 + v.z;
    int sum = e3 + v.w;

    int lane = t & 31, wid = t >> 5;
    int x = sum;
    #pragma unroll
    for (int off = 1; off < 32; off <<= 1) {
        int y = __shfl_up_sync(0xffffffffu, x, off);
        if (lane >= off) x += y;
    }
    if (lane == 31) wsum[wid] = x;
    __syncthreads();
    if (wid == 0) {
        int w = wsum[lane];
        #pragma unroll
        for (int off = 1; off < 32; off <<= 1) {
            int y = __shfl_up_sync(0xffffffffu, w, off);
            if (lane >= off) w += y;
        }
        wsum[lane] = w;
    }
    __syncthreads();
    int pre = x - sum + ((wid > 0) ? wsum[wid - 1] : 0);   // exclusive prefix for elem 0

    int4 o;
    o.x = pre;
    o.y = pre + e1;
    o.z = pre + e2;
    o.w = pre + e3;
    reinterpret_cast<int4*>(out)[t] = o;
}

// ---------------- kernel 3: AP term accumulation (4 records/thread) ----------------
__global__ void k_ap() {
    int idx = blockIdx.x * blockDim.x + threadIdx.x;
    if (idx >= (NBATCH * NB) / 4) return;
    int4 r4 = reinterpret_cast<const int4*>(g_records)[idx];
    int recs[4] = {r4.x, r4.y, r4.z, r4.w};

    #pragma unroll
    for (int k = 0; k < 4; k++) {
        int rec = recs[k];
        if (!(rec & 0x40000000)) continue;
        if (!((rec >> 24) & 1)) continue;

        int c = rec & 0xFF;
        int rank = (rec >> 8) & 0xFF;
        int tpc_loc = (rec >> 16) & 0xFF;
        int gidx = idx * 4 + k;
        int img = gidx / NB;

        int j = g_offv[c * NBATCH + img] + rank + 1;      // 1-based global valid rank
        int tpc = g_offt[c * NBATCH + img] + tpc_loc;     // inclusive cumulative TP

        float pj = (float)tpc / ((float)j + 1e-6f);
        float pprev;
        if (j == 1) {
            pprev = (gidx == 0) ? 1.0f : 0.0f;            // only global position 0 sees prepended p=1
        } else {
            pprev = (float)(tpc - 1) / ((float)(j - 1) + 1e-6f);
        }
        float gt = (float)g_gt[c];
        double term = (double)(pj + pprev) * 0.5 / (double)(gt + 1e-6f);
        atomicAdd(&g_ap[c], term);
    }
}

// ---------------- kernel 4: finalize mAP ----------------
__global__ void k_final(float* out) {
    if (threadIdx.x == 0) {
        double s = 0.0; int n = 0;
        for (int c = 0; c < NC; c++) {
            if (g_gt[c] > 0) { s += g_ap[c]; n++; }
        }
        double nh = (n > 0) ? (double)n : 1.0;
        out[0] = (float)(s / nh);
    }
}

// ---------------- launcher ----------------
extern "C" void kernel_launch(void* const* d_in, const int* in_sizes, int n_in,
                              void* d_out, int out_size) {
    const float* tgt = (const float*)d_in[0];
    const float* outp = (const float*)d_in[1];
    float* out = (float*)d_out;

    k_init<<<1, 32>>>();
    k_per_image<<<NBATCH, 64>>>(tgt, outp);
    k_scan<<<40, 1024>>>();
    k_ap<<<((NBATCH * NB) / 4 + 255) / 256, 256>>>();
    k_final<<<1, 32>>>(out);
}

// round 8
// speedup vs baseline: 1.3786x; 1.2507x over previous
#include <cuda_runtime.h>
#include <math.h>

#define SS 7
#define NB 49          // boxes per image
#define NC 20          // classes
#define NBATCH 4096
#define DD 30          // channels per cell

// ---------------- scratch (device globals; no allocation) ----------------
__device__ __align__(256) int    g_records[NBATCH * NB];   // packed per-pred record
__device__ __align__(256) int    g_nvalid[NC * NBATCH];    // per class, per image valid count
__device__ __align__(256) int    g_ntp[NC * NBATCH];       // per class, per image tp count
__device__ __align__(256) int    g_offv[NC * NBATCH];      // exclusive scans over images
__device__ __align__(256) int    g_offt[NC * NBATCH];
__device__ int    g_gt[NC];                                // per-class GT counts
__device__ double g_ap[NC];                                // per-class AP accumulators

// ---------------- helpers ----------------
__device__ __forceinline__ float sigm(float x) { return 1.0f / (1.0f + expf(-x)); }

__device__ __forceinline__ float iou_v(float ax0, float ay0, float ax1, float ay1, float aar,
                                       float4 b, float bar) {
    float lx = fmaxf(ax0, b.x), ly = fmaxf(ay0, b.y);
    float rx = fminf(ax1, b.z), ry = fminf(ay1, b.w);
    float w = fmaxf(rx - lx, 0.0f), h = fmaxf(ry - ly, 0.0f);
    float inter = w * h;
    return inter / (aar + bar - inter);
}

// ---------------- kernel 0: init ----------------
__global__ void k_init() {
    int t = threadIdx.x;
    if (t < NC) { g_gt[t] = 0; g_ap[t] = 0.0; }
}

// ---------------- kernel 1: per-image pipeline (128 thr; pred-half || GT-half) ----------------
__global__ __launch_bounds__(128) void k_per_image(const float* __restrict__ tgt,
                                                   const float* __restrict__ outp) {
    int img = blockIdx.x;
    int t = threadIdx.x;
    int tb = t - 64;                 // GT-group local index

    __shared__ __align__(16) float stageP[1470];   // pred tensor stage; later aliased
    __shared__ __align__(16) float stageT[1470];   // target tensor stage
    __shared__ float uconf[NB];
    __shared__ float sconf[NB];
    __shared__ __align__(16) float4 sbox[NB];      // sorted pred boxes
    __shared__ __align__(8)  float2 scombo[NB];    // (area, cls-as-int-bits)
    __shared__ __align__(16) float4 gbox[NB];      // GT boxes
    __shared__ __align__(8)  float2 gcombo[NB];    // (area, cls_enc bits; -1 = invalid)
    __shared__ unsigned long long sh_valid, sh_tp;

    // aliases into stageP (dead after pred decode)
    unsigned long long* sup = (unsigned long long*)stageP;  // 392 B
    float* smx   = stageP + 98;                             // +196
    int*   sbest = (int*)(stageP + 147);                    // +196

    // ---- stage both tensors (coalesced float2, 2 streams) ----
    {
        const float2* srcP = reinterpret_cast<const float2*>(outp) + (size_t)img * 735;
        const float2* srcT = reinterpret_cast<const float2*>(tgt)  + (size_t)img * 735;
        float2* dstP = reinterpret_cast<float2*>(stageP);
        float2* dstT = reinterpret_cast<float2*>(stageT);
        for (int i = t; i < 735; i += 128) { dstP[i] = srcP[i]; dstT[i] = srcT[i]; }
    }
    __syncthreads();

    // ---- pred decode (group A) || GT decode (group B) ----
    float bx0 = 0.f, by0 = 0.f, bx1 = 0.f, by1 = 0.f, conf = 0.f;
    int cls = 0;
    if (t < NB) {
        const float* o = stageP + t * DD;
        float c0 = sigm(o[4]);
        float c1 = sigm(o[9]);
        int resp = (c1 > c0) ? 1 : 0;
        conf = resp ? c1 : c0;
        const float* oc = o + resp * 5;
        float px = sigm(oc[0]), py = sigm(oc[1]), pw = sigm(oc[2]), ph = sigm(oc[3]);
        int iy = t / SS, jx = t % SS;
        float cx = (px + (float)jx) * 64.0f;
        float cy = (py + (float)iy) * 64.0f;
        float W = pw * 448.0f, H = ph * 448.0f;
        bx0 = cx - W * 0.5f; by0 = cy - H * 0.5f;
        bx1 = cx + W * 0.5f; by1 = cy + H * 0.5f;
        uconf[t] = conf;
        float bm = o[10]; int bi = 0;
        #pragma unroll
        for (int k = 1; k < NC; k++) { float v = o[10 + k]; if (v > bm) { bm = v; bi = k; } }
        cls = bi;
    } else if (tb >= 0 && tb < NB) {
        const float* g = stageT + tb * DD;
        int valid = (g[4] > 0.5f) ? 1 : 0;
        int iy = tb / SS, jx = tb % SS;
        float cx = (g[0] + (float)jx) * 64.0f;
        float cy = (g[1] + (float)iy) * 64.0f;
        float W = g[2] * 448.0f, H = g[3] * 448.0f;
        float x0 = cx - W * 0.5f, y0 = cy - H * 0.5f;
        float x1 = cx + W * 0.5f, y1 = cy + H * 0.5f;
        gbox[tb] = make_float4(x0, y0, x1, y1);
        float gm = g[10]; int gi = 0;
        #pragma unroll
        for (int k = 1; k < NC; k++) { float v = g[10 + k]; if (v > gm) { gm = v; gi = k; } }
        int enc = valid ? gi : -1;
        gcombo[tb] = make_float2((x1 - x0) * (y1 - y0), __int_as_float(enc));
    }
    __syncthreads();

    // ---- stable sort by conf desc: rank-count + direct scatter (group A) ----
    if (t < NB) {
        int r = 0;
        float ci = conf;
        for (int j = 0; j < NB; j++) {
            float cj = uconf[j];
            r += (cj > ci) || (cj == ci && j < t);
        }
        sconf[r] = ci;
        sbox[r] = make_float4(bx0, by0, bx1, by1);
        scombo[r] = make_float2((bx1 - bx0) * (by1 - by0), __int_as_float(cls));
    }
    __syncthreads();   // stageP dead from here; sup/smx/sbest live

    // ---- NMS rows (group A) || best-GT IoU (group B), both over sorted preds ----
    if (t < NB) {
        float4 a = sbox[t];
        float2 ac = scombo[t];
        int c = __float_as_int(ac.y);
        unsigned long long m = 0ull;
        for (int j = 0; j < NB; j++) {
            float4 b = sbox[j];
            float2 bc = scombo[j];
            if (__float_as_int(bc.y) == c &&
                iou_v(a.x, a.y, a.z, a.w, ac.x, b, bc.x) > 0.5f)
                m |= (1ull << j);
        }
        sup[t] = m;
    } else if (tb >= 0 && tb < NB) {
        float4 a = sbox[tb];
        float2 ac = scombo[tb];
        int c = __float_as_int(ac.y);
        float mx = -1.0f; int best = 0;
        for (int g = 0; g < NB; g++) {
            float4 gg = gbox[g];
            float2 gc = gcombo[g];
            if (__float_as_int(gc.y) == c) {
                float v = iou_v(a.x, a.y, a.z, a.w, ac.x, gg, gc.x);
                if (v > mx) { mx = v; best = g; }
            }
        }
        smx[tb] = mx; sbest[tb] = best;
    }
    __syncthreads();

    // ---- serial greedy NMS + TP matching (thread 0) ----
    if (t == 0) {
        unsigned long long suppressed = 0ull, keep = 0ull;
        for (int i = 0; i < NB; i++) {
            if (!((suppressed >> i) & 1ull)) {
                keep |= (1ull << i);
                suppressed |= sup[i] & ~((2ull << i) - 1ull);
            }
        }
        unsigned long long valid = 0ull;
        for (int i = 0; i < NB; i++)
            if (((keep >> i) & 1ull) && sconf[i] > 0.5f) valid |= (1ull << i);

        unsigned long long matched = 0ull, tpm = 0ull;
        for (int i = 0; i < NB; i++) {
            if (((valid >> i) & 1ull) && smx[i] > 0.5f && !((matched >> sbest[i]) & 1ull)) {
                matched |= (1ull << sbest[i]);
                tpm |= (1ull << i);
            }
        }
        sh_valid = valid; sh_tp = tpm;
    }
    __syncthreads();

    unsigned long long vm = sh_valid, tm = sh_tp;

    // ---- records (group A) || per-class counts + GT counts (group B) ----
    if (t < NB) {
        int rec = 0;
        if ((vm >> t) & 1ull) {
            int c = __float_as_int(scombo[t].y);
            int rank = 0, tpc = 0;
            for (int j = 0; j <= t; j++) {
                if (((vm >> j) & 1ull) && __float_as_int(scombo[j].y) == c) {
                    if (j < t) rank++;
                    tpc += (int)((tm >> j) & 1ull);
                }
            }
            int tp = (int)((tm >> t) & 1ull);
            rec = 0x40000000 | c | (rank << 8) | (tpc << 16) | (tp << 24);
        }
        g_records[img * NB + t] = rec;
    } else if (tb >= 0 && tb < NC) {
        int nv = 0, nt = 0, ng = 0;
        for (int j = 0; j < NB; j++) {
            if (((vm >> j) & 1ull) && __float_as_int(scombo[j].y) == tb) {
                nv++;
                nt += (int)((tm >> j) & 1ull);
            }
            if (__float_as_int(gcombo[j].y) == tb) ng++;
        }
        g_nvalid[tb * NBATCH + img] = nv;
        g_ntp[tb * NBATCH + img] = nt;
        if (ng) atomicAdd(&g_gt[tb], ng);
    }
}

// ---------------- kernel 2: exclusive scan over images per (class, kind) ----------------
__global__ __launch_bounds__(1024) void k_scan() {
    __shared__ int wsum[32];
    int bx = blockIdx.x;            // 0..39
    int t = threadIdx.x;            // 1024 threads x 4 elems = 4096
    const int* in = (bx < NC) ? (g_nvalid + bx * NBATCH) : (g_ntp + (bx - NC) * NBATCH);
    int* out = (bx < NC) ? (g_offv + bx * NBATCH) : (g_offt + (bx - NC) * NBATCH);

    int4 v = reinterpret_cast<const int4*>(in)[t];
    int e1 = v.x, e2 = e1 + v.y, e3 = e2 + v.z;
    int sum = e3 + v.w;

    int lane = t & 31, wid = t >> 5;
    int x = sum;
    #pragma unroll
    for (int off = 1; off < 32; off <<= 1) {
        int y = __shfl_up_sync(0xffffffffu, x, off);
        if (lane >= off) x += y;
    }
    if (lane == 31) wsum[wid] = x;
    __syncthreads();
    if (wid == 0) {
        int w = wsum[lane];
        #pragma unroll
        for (int off = 1; off < 32; off <<= 1) {
            int y = __shfl_up_sync(0xffffffffu, w, off);
            if (lane >= off) w += y;
        }
        wsum[lane] = w;
    }
    __syncthreads();
    int pre = x - sum + ((wid > 0) ? wsum[wid - 1] : 0);   // exclusive prefix for elem 0

    int4 o;
    o.x = pre;
    o.y = pre + e1;
    o.z = pre + e2;
    o.w = pre + e3;
    reinterpret_cast<int4*>(out)[t] = o;
}

// ---------------- kernel 3: AP term accumulation (1 record/thread; occupancy wins) ----------------
__global__ void k_ap() {
    int idx = blockIdx.x * blockDim.x + threadIdx.x;
    if (idx >= NBATCH * NB) return;
    int rec = g_records[idx];
    if (!(rec & 0x40000000)) return;
    if (!((rec >> 24) & 1)) return;

    int c = rec & 0xFF;
    int rank = (rec >> 8) & 0xFF;
    int tpc_loc = (rec >> 16) & 0xFF;
    int img = idx / NB;

    int j = g_offv[c * NBATCH + img] + rank + 1;      // 1-based global valid rank
    int tpc = g_offt[c * NBATCH + img] + tpc_loc;     // inclusive cumulative TP

    float pj = (float)tpc / ((float)j + 1e-6f);
    float pprev;
    if (j == 1) {
        pprev = (idx == 0) ? 1.0f : 0.0f;             // only global position 0 sees prepended p=1
    } else {
        pprev = (float)(tpc - 1) / ((float)(j - 1) + 1e-6f);
    }
    float gt = (float)g_gt[c];
    double term = (double)(pj + pprev) * 0.5 / (double)(gt + 1e-6f);
    atomicAdd(&g_ap[c], term);
}

// ---------------- kernel 4: finalize mAP ----------------
__global__ void k_final(float* out) {
    if (threadIdx.x == 0) {
        double s = 0.0; int n = 0;
        for (int c = 0; c < NC; c++) {
            if (g_gt[c] > 0) { s += g_ap[c]; n++; }
        }
        double nh = (n > 0) ? (double)n : 1.0;
        out[0] = (float)(s / nh);
    }
}

// ---------------- launcher ----------------
extern "C" void kernel_launch(void* const* d_in, const int* in_sizes, int n_in,
                              void* d_out, int out_size) {
    const float* tgt = (const float*)d_in[0];
    const float* outp = (const float*)d_in[1];
    float* out = (float*)d_out;

    k_init<<<1, 32>>>();
    k_per_image<<<NBATCH, 128>>>(tgt, outp);
    k_scan<<<40, 1024>>>();
    k_ap<<<(NBATCH * NB + 255) / 256, 256>>>();
    k_final<<<1, 32>>>(out);
}

// round 9
// speedup vs baseline: 1.6715x; 1.2125x over previous
#include <cuda_runtime.h>
#include <math.h>

#define SS 7
#define NB 49          // boxes per image
#define NC 20          // classes
#define NBATCH 4096
#define DD 30          // channels per cell

// ---------------- scratch (device globals; no allocation) ----------------
__device__ __align__(256) int    g_records[NBATCH * NB];   // packed per-pred record
__device__ __align__(256) int    g_nvalid[NC * NBATCH];    // per class, per image valid count
__device__ __align__(256) int    g_ntp[NC * NBATCH];       // per class, per image tp count
__device__ __align__(256) int    g_offv[NC * NBATCH];      // exclusive scans over images
__device__ __align__(256) int    g_offt[NC * NBATCH];
__device__ int    g_gt[NC];                                // per-class GT counts
__device__ double g_ap[NC];                                // per-class AP accumulators

// ---------------- helpers ----------------
__device__ __forceinline__ float sigm(float x) { return 1.0f / (1.0f + expf(-x)); }

__device__ __forceinline__ float iou_v(float ax0, float ay0, float ax1, float ay1, float aar,
                                       float4 b, float bar) {
    float lx = fmaxf(ax0, b.x), ly = fmaxf(ay0, b.y);
    float rx = fminf(ax1, b.z), ry = fminf(ay1, b.w);
    float w = fmaxf(rx - lx, 0.0f), h = fmaxf(ry - ly, 0.0f);
    float inter = w * h;
    return inter / (aar + bar - inter);
}

// ---------------- kernel 0: init ----------------
__global__ void k_init() {
    int t = threadIdx.x;
    if (t < NC) { g_gt[t] = 0; g_ap[t] = 0.0; }
}

// ---------------- kernel 1: per-image pipeline ----------------
// 128 threads. Group A = warps 0-1 (t<64), Group B = warps 2-3.
__global__ __launch_bounds__(128) void k_per_image(const float* __restrict__ tgt,
                                                   const float* __restrict__ outp) {
    int img = blockIdx.x;
    int t = threadIdx.x;
    int tb = t - 64;                 // B-group local index

    __shared__ __align__(16) float stageP[1470];   // pred tensor stage; aliased after P1
    __shared__ __align__(16) float stageT[1470];   // target tensor stage
    __shared__ float uconf[NB];
    __shared__ __align__(16) float4 ubox[NB];      // unsorted pred boxes (for B's GT-IoU)
    __shared__ __align__(8)  float2 ucombo[NB];    // unsorted (area, cls bits)
    __shared__ float sconf[NB];
    __shared__ __align__(16) float4 sbox[NB];      // sorted pred boxes
    __shared__ __align__(8)  float2 scombo[NB];    // sorted (area, cls bits)
    __shared__ __align__(16) float4 gbox[NB];      // GT boxes
    __shared__ __align__(8)  float2 gcombo[NB];    // (area, cls_enc bits; -1 = invalid)
    __shared__ int sbest[NB];                      // best GT index per sorted pred
    __shared__ unsigned long long clsmask[NC];     // sorted-pred membership per class
    __shared__ unsigned long long gclsmask[NC];    // valid-GT membership per class
    __shared__ unsigned long long sh_valid, sh_tp;

    // aliases into stageP (pred stage dead after P1)
    unsigned long long* sup_a = (unsigned long long*)stageP;          // floats 0..97
    unsigned long long* sup_b = (unsigned long long*)(stageP + 98);   // 98..195
    float* umx    = stageP + 196;                                     // 196..244
    int*   ubest  = (int*)(stageP + 245);                             // 245..293
    int*   srcidx = (int*)(stageP + 294);                             // 294..342
    unsigned* ballots = (unsigned*)(stageP + 343);                    // 4 words

    // zero class masks (read only in P5; written from P1/P2)
    if (t < NC) clsmask[t] = 0ull;
    else if (t >= 32 && t < 32 + NC) gclsmask[t - 32] = 0ull;

    // ---- P0: stage both tensors (coalesced float2, 2 streams) ----
    {
        const float2* srcP = reinterpret_cast<const float2*>(outp) + (size_t)img * 735;
        const float2* srcT = reinterpret_cast<const float2*>(tgt)  + (size_t)img * 735;
        float2* dstP = reinterpret_cast<float2*>(stageP);
        float2* dstT = reinterpret_cast<float2*>(stageT);
        for (int i = t; i < 735; i += 128) { dstP[i] = srcP[i]; dstT[i] = srcT[i]; }
    }
    __syncthreads();

    // ---- P1: pred decode (A) || GT decode (B) ----
    float bx0 = 0.f, by0 = 0.f, bx1 = 0.f, by1 = 0.f, conf = 0.f, area = 0.f;
    int cls = 0;
    if (t < NB) {
        const float* o = stageP + t * DD;
        float c0 = sigm(o[4]);
        float c1 = sigm(o[9]);
        int resp = (c1 > c0) ? 1 : 0;
        conf = resp ? c1 : c0;
        const float* oc = o + resp * 5;
        float px = sigm(oc[0]), py = sigm(oc[1]), pw = sigm(oc[2]), ph = sigm(oc[3]);
        int iy = t / SS, jx = t % SS;
        float cx = (px + (float)jx) * 64.0f;
        float cy = (py + (float)iy) * 64.0f;
        float W = pw * 448.0f, H = ph * 448.0f;
        bx0 = cx - W * 0.5f; by0 = cy - H * 0.5f;
        bx1 = cx + W * 0.5f; by1 = cy + H * 0.5f;
        area = (bx1 - bx0) * (by1 - by0);
        uconf[t] = conf;
        float bm = o[10]; int bi = 0;
        #pragma unroll
        for (int k = 1; k < NC; k++) { float v = o[10 + k]; if (v > bm) { bm = v; bi = k; } }
        cls = bi;
        ubox[t] = make_float4(bx0, by0, bx1, by1);
        ucombo[t] = make_float2(area, __int_as_float(cls));
    } else if (tb >= 0 && tb < NB) {
        const float* g = stageT + tb * DD;
        int valid = (g[4] > 0.5f) ? 1 : 0;
        int iy = tb / SS, jx = tb % SS;
        float cx = (g[0] + (float)jx) * 64.0f;
        float cy = (g[1] + (float)iy) * 64.0f;
        float W = g[2] * 448.0f, H = g[3] * 448.0f;
        float x0 = cx - W * 0.5f, y0 = cy - H * 0.5f;
        float x1 = cx + W * 0.5f, y1 = cy + H * 0.5f;
        gbox[tb] = make_float4(x0, y0, x1, y1);
        float gm = g[10]; int gi = 0;
        #pragma unroll
        for (int k = 1; k < NC; k++) { float v = g[10 + k]; if (v > gm) { gm = v; gi = k; } }
        int enc = valid ? gi : -1;
        gcombo[tb] = make_float2((x1 - x0) * (y1 - y0), __int_as_float(enc));
        if (enc >= 0) atomicOr(&gclsmask[enc], 1ull << tb);
    }
    __syncthreads();

    // ---- P2: A: stable sort-scatter  ||  B: GT-IoU in UNSORTED pred space ----
    if (t < NB) {
        int r = 0;
        float ci = conf;
        for (int j = 0; j < NB; j++) {
            float cj = uconf[j];
            r += (cj > ci) || (cj == ci && j < t);
        }
        sconf[r] = ci;
        sbox[r] = make_float4(bx0, by0, bx1, by1);
        scombo[r] = make_float2(area, __int_as_float(cls));
        srcidx[r] = t;
        atomicOr(&clsmask[cls], 1ull << r);
    } else if (tb >= 0 && tb < NB) {
        float4 a = ubox[tb];
        float2 ac = ucombo[tb];
        int c = __float_as_int(ac.y);
        float mx = -1.0f; int best = 0;
        for (int g = 0; g < NB; g++) {
            float2 gc = gcombo[g];
            if (__float_as_int(gc.y) == c) {
                float v = iou_v(a.x, a.y, a.z, a.w, ac.x, gbox[g], gc.x);
                if (v > mx) { mx = v; best = g; }
            }
        }
        umx[tb] = mx; ubest[tb] = best;
    }
    __syncthreads();

    // ---- P3: split NMS rows (j>t only), permute GT match into sorted order, ballots ----
    if (t < 64) {
        float cf = 0.f, mxv = -1.0f;
        if (t < NB) {
            float4 a = sbox[t];
            float2 ac = scombo[t];
            int c = __float_as_int(ac.y);
            int mid = (t + NB) >> 1;                 // A covers (t, mid], B covers (mid, NB)
            unsigned long long m = 0ull;
            for (int j = t + 1; j <= mid; j++) {
                float2 bc = scombo[j];
                if (__float_as_int(bc.y) == c &&
                    iou_v(a.x, a.y, a.z, a.w, ac.x, sbox[j], bc.x) > 0.5f)
                    m |= (1ull << j);
            }
            sup_a[t] = m;
            int s = srcidx[t];
            mxv = umx[s];
            sbest[t] = ubest[s];
            cf = sconf[t];
        }
        unsigned bc0 = __ballot_sync(0xffffffffu, (t < NB) && (cf > 0.5f));
        unsigned bc1 = __ballot_sync(0xffffffffu, (t < NB) && (mxv > 0.5f));
        if ((t & 31) == 0) { ballots[(t >> 5) * 2] = bc0; ballots[(t >> 5) * 2 + 1] = bc1; }
    } else if (tb < NB) {
        float4 a = sbox[tb];
        float2 ac = scombo[tb];
        int c = __float_as_int(ac.y);
        int mid = (tb + NB) >> 1;
        unsigned long long m = 0ull;
        for (int j = mid + 1; j < NB; j++) {
            float2 bc = scombo[j];
            if (__float_as_int(bc.y) == c &&
                iou_v(a.x, a.y, a.z, a.w, ac.x, sbox[j], bc.x) > 0.5f)
                m |= (1ull << j);
        }
        sup_b[tb] = m;
    }
    __syncthreads();

    // ---- P4: serial greedy NMS + TP matching via bit-scans (thread 0) ----
    if (t == 0) {
        unsigned long long confmask = (unsigned long long)ballots[0] |
                                      ((unsigned long long)ballots[2] << 32);
        unsigned long long candmask = (unsigned long long)ballots[1] |
                                      ((unsigned long long)ballots[3] << 32);
        unsigned long long rem = (1ull << NB) - 1ull, keep = 0ull;
        while (rem) {
            int i = __ffsll((long long)rem) - 1;
            keep |= (1ull << i);
            rem &= ~(sup_a[i] | sup_b[i] | (1ull << i));
        }
        unsigned long long valid = keep & confmask;
        unsigned long long cand = valid & candmask;
        unsigned long long matched = 0ull, tpm = 0ull;
        while (cand) {
            int i = __ffsll((long long)cand) - 1;
            cand &= cand - 1ull;
            int b = sbest[i];
            if (!((matched >> b) & 1ull)) {
                matched |= (1ull << b);
                tpm |= (1ull << i);
            }
        }
        sh_valid = valid; sh_tp = tpm;
    }
    __syncthreads();

    unsigned long long vm = sh_valid, tm = sh_tp;

    // ---- P5: records (A, O(1) popcounts) || per-class counts (B, O(1) popcounts) ----
    if (t < NB) {
        int rec = 0;
        if ((vm >> t) & 1ull) {
            int c = __float_as_int(scombo[t].y);
            unsigned long long cm = clsmask[c];
            int rank = __popcll(vm & cm & ((1ull << t) - 1ull));
            int tpc  = __popcll(tm & cm & ((2ull << t) - 1ull));
            int tp = (int)((tm >> t) & 1ull);
            rec = 0x40000000 | c | (rank << 8) | (tpc << 16) | (tp << 24);
        }
        g_records[img * NB + t] = rec;
    } else if (tb >= 0 && tb < NC) {
        unsigned long long cm = clsmask[tb];
        g_nvalid[tb * NBATCH + img] = __popcll(vm & cm);
        g_ntp[tb * NBATCH + img]    = __popcll(tm & cm);
        int ng = __popcll(gclsmask[tb]);
        if (ng) atomicAdd(&g_gt[tb], ng);
    }
}

// ---------------- kernel 2: exclusive scan over images per (class, kind) ----------------
__global__ __launch_bounds__(1024) void k_scan() {
    __shared__ int wsum[32];
    int bx = blockIdx.x;            // 0..39
    int t = threadIdx.x;            // 1024 threads x 4 elems = 4096
    const int* in = (bx < NC) ? (g_nvalid + bx * NBATCH) : (g_ntp + (bx - NC) * NBATCH);
    int* out = (bx < NC) ? (g_offv + bx * NBATCH) : (g_offt + (bx - NC) * NBATCH);

    int4 v = reinterpret_cast<const int4*>(in)[t];
    int e1 = v.x, e2 = e1 + v.y, e3 = e2 + v.z;
    int sum = e3 + v.w;

    int lane = t & 31, wid = t >> 5;
    int x = sum;
    #pragma unroll
    for (int off = 1; off < 32; off <<= 1) {
        int y = __shfl_up_sync(0xffffffffu, x, off);
        if (lane >= off) x += y;
    }
    if (lane == 31) wsum[wid] = x;
    __syncthreads();
    if (wid == 0) {
        int w = wsum[lane];
        #pragma unroll
        for (int off = 1; off < 32; off <<= 1) {
            int y = __shfl_up_sync(0xffffffffu, w, off);
            if (lane >= off) w += y;
        }
        wsum[lane] = w;
    }
    __syncthreads();
    int pre = x - sum + ((wid > 0) ? wsum[wid - 1] : 0);   // exclusive prefix for elem 0

    int4 o;
    o.x = pre;
    o.y = pre + e1;
    o.z = pre + e2;
    o.w = pre + e3;
    reinterpret_cast<int4*>(out)[t] = o;
}

// ---------------- kernel 3: AP term accumulation ----------------
__global__ void k_ap() {
    int idx = blockIdx.x * blockDim.x + threadIdx.x;
    if (idx >= NBATCH * NB) return;
    int rec = g_records[idx];
    if (!(rec & 0x40000000)) return;
    if (!((rec >> 24) & 1)) return;

    int c = rec & 0xFF;
    int rank = (rec >> 8) & 0xFF;
    int tpc_loc = (rec >> 16) & 0xFF;
    int img = idx / NB;

    int j = g_offv[c * NBATCH + img] + rank + 1;      // 1-based global valid rank
    int tpc = g_offt[c * NBATCH + img] + tpc_loc;     // inclusive cumulative TP

    float pj = (float)tpc / ((float)j + 1e-6f);
    float pprev;
    if (j == 1) {
        pprev = (idx == 0) ? 1.0f : 0.0f;             // only global position 0 sees prepended p=1
    } else {
        pprev = (float)(tpc - 1) / ((float)(j - 1) + 1e-6f);
    }
    float gt = (float)g_gt[c];
    double term = (double)(pj + pprev) * 0.5 / (double)(gt + 1e-6f);
    atomicAdd(&g_ap[c], term);
}

// ---------------- kernel 4: finalize mAP ----------------
__global__ void k_final(float* out) {
    if (threadIdx.x == 0) {
        double s = 0.0; int n = 0;
        for (int c = 0; c < NC; c++) {
            if (g_gt[c] > 0) { s += g_ap[c]; n++; }
        }
        double nh = (n > 0) ? (double)n : 1.0;
        out[0] = (float)(s / nh);
    }
}

// ---------------- launcher ----------------
extern "C" void kernel_launch(void* const* d_in, const int* in_sizes, int n_in,
                              void* d_out, int out_size) {
    const float* tgt = (const float*)d_in[0];
    const float* outp = (const float*)d_in[1];
    float* out = (float*)d_out;

    k_init<<<1, 32>>>();
    k_per_image<<<NBATCH, 128>>>(tgt, outp);
    k_scan<<<40, 1024>>>();
    k_ap<<<(NBATCH * NB + 255) / 256, 256>>>();
    k_final<<<1, 32>>>(out);
}

// round 10
// speedup vs baseline: 2.4581x; 1.4706x over previous
#include <cuda_runtime.h>
#include <math.h>

#define SS 7
#define NB 49          // boxes per image
#define NC 20          // classes
#define NBATCH 4096
#define DD 30          // channels per cell

// ---------------- scratch (device globals; no allocation) ----------------
__device__ __align__(256) int    g_records[NBATCH * NB];   // packed per-pred record
__device__ __align__(256) int    g_nvalid[NC * NBATCH];    // per class, per image valid count
__device__ __align__(256) int    g_ntp[NC * NBATCH];       // per class, per image tp count
__device__ __align__(256) int    g_ngt[NC * NBATCH];       // per class, per image GT count
__device__ __align__(256) int    g_offv[NC * NBATCH];      // exclusive scans over images
__device__ __align__(256) int    g_offt[NC * NBATCH];
__device__ int    g_gt[NC];                                // per-class GT totals (from k_scan)
__device__ double g_ap[NC];                                // per-class AP accumulators

// ---------------- helpers ----------------
__device__ __forceinline__ float sigm(float x) { return 1.0f / (1.0f + expf(-x)); }

__device__ __forceinline__ float iou_v(float ax0, float ay0, float ax1, float ay1, float aar,
                                       float4 b, float bar) {
    float lx = fmaxf(ax0, b.x), ly = fmaxf(ay0, b.y);
    float rx = fminf(ax1, b.z), ry = fminf(ay1, b.w);
    float w = fmaxf(rx - lx, 0.0f), h = fmaxf(ry - ly, 0.0f);
    float inter = w * h;
    return inter / (aar + bar - inter);
}

// ---------------- kernel 1: per-image pipeline ----------------
// 128 threads. Group A = warps 0-1 (t<64), Group B = warps 2-3.
__global__ __launch_bounds__(128) void k_per_image(const float* __restrict__ tgt,
                                                   const float* __restrict__ outp) {
    int img = blockIdx.x;
    int t = threadIdx.x;
    int tb = t - 64;                 // B-group local index

    __shared__ __align__(16) float stageP[1470];   // pred tensor stage; aliased after P1
    __shared__ __align__(16) float stageT[1470];   // target tensor stage
    __shared__ float uconf[NB];
    __shared__ __align__(16) float4 ubox[NB];      // unsorted pred boxes
    __shared__ __align__(8)  float2 ucombo[NB];    // unsorted (area, cls bits)
    __shared__ __align__(16) float4 sbox[NB];      // sorted pred boxes
    __shared__ __align__(8)  float2 scombo[NB];    // sorted (area, cls bits)
    __shared__ __align__(16) float4 gbox[NB];      // GT boxes
    __shared__ __align__(8)  float2 gcombo[NB];    // (area, cls bits; unused after P2)
    __shared__ int sbest[NB];                      // best GT index per sorted pred (-1 = none)
    __shared__ unsigned long long clsmask[NC];     // sorted-pred membership per class
    __shared__ unsigned long long gclsmask[NC];    // valid-GT membership per class
    __shared__ unsigned long long sh_conf, sh_valid, sh_tp;

    // aliases into stageP (pred stage dead after P1)
    unsigned long long* sup = (unsigned long long*)stageP;   // floats 0..97   (j>t bits only)
    int*   srcidx = (int*)(stageP + 98);                     // 98..146
    int*   ubest  = (int*)(stageP + 147);                    // 147..195
    unsigned* ballots = (unsigned*)(stageP + 196);           // 2 words

    if (t < NC) clsmask[t] = 0ull;
    else if (t >= 32 && t < 32 + NC) gclsmask[t - 32] = 0ull;
    else if (t == 63) sh_conf = 0ull;

    // ---- P0: stage both tensors (coalesced float2, 2 streams) ----
    {
        const float2* srcP = reinterpret_cast<const float2*>(outp) + (size_t)img * 735;
        const float2* srcT = reinterpret_cast<const float2*>(tgt)  + (size_t)img * 735;
        float2* dstP = reinterpret_cast<float2*>(stageP);
        float2* dstT = reinterpret_cast<float2*>(stageT);
        for (int i = t; i < 735; i += 128) { dstP[i] = srcP[i]; dstT[i] = srcT[i]; }
    }
    __syncthreads();

    // ---- P1: pred decode (A) || GT decode + class masks (B) ----
    float bx0 = 0.f, by0 = 0.f, bx1 = 0.f, by1 = 0.f, conf = 0.f, area = 0.f;
    int cls = 0;
    if (t < NB) {
        const float* o = stageP + t * DD;
        float c0 = sigm(o[4]);
        float c1 = sigm(o[9]);
        int resp = (c1 > c0) ? 1 : 0;
        conf = resp ? c1 : c0;
        const float* oc = o + resp * 5;
        float px = sigm(oc[0]), py = sigm(oc[1]), pw = sigm(oc[2]), ph = sigm(oc[3]);
        int iy = t / SS, jx = t % SS;
        float cx = (px + (float)jx) * 64.0f;
        float cy = (py + (float)iy) * 64.0f;
        float W = pw * 448.0f, H = ph * 448.0f;
        bx0 = cx - W * 0.5f; by0 = cy - H * 0.5f;
        bx1 = cx + W * 0.5f; by1 = cy + H * 0.5f;
        area = (bx1 - bx0) * (by1 - by0);
        uconf[t] = conf;
        float bm = o[10]; int bi = 0;
        #pragma unroll
        for (int k = 1; k < NC; k++) { float v = o[10 + k]; if (v > bm) { bm = v; bi = k; } }
        cls = bi;
        ubox[t] = make_float4(bx0, by0, bx1, by1);
        ucombo[t] = make_float2(area, __int_as_float(cls));
    } else if (tb >= 0 && tb < NB) {
        const float* g = stageT + tb * DD;
        int valid = (g[4] > 0.5f) ? 1 : 0;
        int iy = tb / SS, jx = tb % SS;
        float cx = (g[0] + (float)jx) * 64.0f;
        float cy = (g[1] + (float)iy) * 64.0f;
        float W = g[2] * 448.0f, H = g[3] * 448.0f;
        float x0 = cx - W * 0.5f, y0 = cy - H * 0.5f;
        float x1 = cx + W * 0.5f, y1 = cy + H * 0.5f;
        gbox[tb] = make_float4(x0, y0, x1, y1);
        float gm = g[10]; int gi = 0;
        #pragma unroll
        for (int k = 1; k < NC; k++) { float v = g[10 + k]; if (v > gm) { gm = v; gi = k; } }
        gcombo[tb] = make_float2((x1 - x0) * (y1 - y0), 0.0f);
        if (valid) atomicOr(&gclsmask[gi], 1ull << tb);
    }
    __syncthreads();

    // ---- P2: A: stable sort-scatter + masks || B: GT-IoU via gclsmask bit-loop ----
    if (t < NB) {
        int r = 0;
        float ci = conf;
        #pragma unroll
        for (int j = 0; j < NB; j++) {
            float cj = uconf[j];
            r += (cj > ci) || (cj == ci && j < t);
        }
        sbox[r] = make_float4(bx0, by0, bx1, by1);
        scombo[r] = make_float2(area, __int_as_float(cls));
        srcidx[r] = t;
        atomicOr(&clsmask[cls], 1ull << r);
        if (ci > 0.5f) atomicOr(&sh_conf, 1ull << r);
    } else if (tb >= 0 && tb < NB) {
        float4 a = ubox[tb];
        float2 ac = ucombo[tb];
        int c = __float_as_int(ac.y);
        unsigned long long m = gclsmask[c];
        float mx = -1.0f; int best = -1;
        while (m) {
            int g = __ffsll((long long)m) - 1;
            m &= m - 1ull;
            float v = iou_v(a.x, a.y, a.z, a.w, ac.x, gbox[g], gcombo[g].x);
            if (v > mx) { mx = v; best = g; }
        }
        ubest[tb] = (mx > 0.5f) ? best : -1;
    }
    __syncthreads();

    // ---- P3: NMS rows via clsmask bit-loop (j>t only) + sbest permute + cand ballot ----
    if (t < 64) {
        int bflag = 0;
        if (t < NB) {
            float4 a = sbox[t];
            float2 ac = scombo[t];
            int c = __float_as_int(ac.y);
            unsigned long long cand = clsmask[c] & ~((2ull << t) - 1ull);  // bits j>t
            unsigned long long m = 0ull;
            while (cand) {
                int j = __ffsll((long long)cand) - 1;
                cand &= cand - 1ull;
                if (iou_v(a.x, a.y, a.z, a.w, ac.x, sbox[j], scombo[j].x) > 0.5f)
                    m |= (1ull << j);
            }
            sup[t] = m;
            int b = ubest[srcidx[t]];
            sbest[t] = b;
            bflag = (b >= 0);
        }
        unsigned bc = __ballot_sync(0xffffffffu, bflag);
        if ((t & 31) == 0) ballots[t >> 5] = bc;
    }
    __syncthreads();

    // ---- P4: serial greedy NMS + TP matching via bit-scans (thread 0) ----
    if (t == 0) {
        unsigned long long candm = (unsigned long long)ballots[0] |
                                   ((unsigned long long)ballots[1] << 32);
        unsigned long long rem = (1ull << NB) - 1ull, keep = 0ull;
        while (rem) {
            int i = __ffsll((long long)rem) - 1;
            keep |= (1ull << i);
            rem &= ~(sup[i] | (1ull << i));
        }
        unsigned long long valid = keep & sh_conf;
        unsigned long long cand = valid & candm;
        unsigned long long matched = 0ull, tpm = 0ull;
        while (cand) {
            int i = __ffsll((long long)cand) - 1;
            cand &= cand - 1ull;
            int b = sbest[i];
            if (!((matched >> b) & 1ull)) {
                matched |= (1ull << b);
                tpm |= (1ull << i);
            }
        }
        sh_valid = valid; sh_tp = tpm;
    }
    __syncthreads();

    unsigned long long vm = sh_valid, tm = sh_tp;

    // ---- P5: records (A) || per-class counts incl. GT (B), all O(1) popcounts ----
    if (t < NB) {
        int rec = 0;
        if ((vm >> t) & 1ull) {
            int c = __float_as_int(scombo[t].y);
            unsigned long long cm = clsmask[c];
            int rank = __popcll(vm & cm & ((1ull << t) - 1ull));
            int tpc  = __popcll(tm & cm & ((2ull << t) - 1ull));
            int tp = (int)((tm >> t) & 1ull);
            rec = 0x40000000 | c | (rank << 8) | (tpc << 16) | (tp << 24);
        }
        g_records[img * NB + t] = rec;
    } else if (tb >= 0 && tb < NC) {
        unsigned long long cm = clsmask[tb];
        g_nvalid[tb * NBATCH + img] = __popcll(vm & cm);
        g_ntp[tb * NBATCH + img]    = __popcll(tm & cm);
        g_ngt[tb * NBATCH + img]    = __popcll(gclsmask[tb]);
    }
}

// ---------------- kernel 2: scans (nvalid, ntp) + GT totals + g_ap zero ----------------
__global__ __launch_bounds__(1024) void k_scan() {
    __shared__ int wsum[32];
    int bx = blockIdx.x;            // 0..59
    int t = threadIdx.x;            // 1024 threads x 4 elems = 4096

    if (bx == 0 && t < NC) g_ap[t] = 0.0;

    const int* in;
    if (bx < NC)          in = g_nvalid + bx * NBATCH;
    else if (bx < 2 * NC) in = g_ntp + (bx - NC) * NBATCH;
    else                  in = g_ngt + (bx - 2 * NC) * NBATCH;

    int4 v = reinterpret_cast<const int4*>(in)[t];
    int e1 = v.x, e2 = e1 + v.y, e3 = e2 + v.z;
    int sum = e3 + v.w;

    int lane = t & 31, wid = t >> 5;
    int x = sum;
    #pragma unroll
    for (int off = 1; off < 32; off <<= 1) {
        int y = __shfl_up_sync(0xffffffffu, x, off);
        if (lane >= off) x += y;
    }
    if (lane == 31) wsum[wid] = x;
    __syncthreads();
    if (wid == 0) {
        int w = wsum[lane];
        #pragma unroll
        for (int off = 1; off < 32; off <<= 1) {
            int y = __shfl_up_sync(0xffffffffu, w, off);
            if (lane >= off) w += y;
        }
        wsum[lane] = w;
    }
    __syncthreads();
    int pre = x - sum + ((wid > 0) ? wsum[wid - 1] : 0);   // exclusive prefix for elem 0

    if (bx < 2 * NC) {
        int* out = (bx < NC) ? (g_offv + bx * NBATCH) : (g_offt + (bx - NC) * NBATCH);
        int4 o;
        o.x = pre;
        o.y = pre + e1;
        o.z = pre + e2;
        o.w = pre + e3;
        reinterpret_cast<int4*>(out)[t] = o;
    } else {
        if (t == 1023) g_gt[bx - 2 * NC] = pre + sum;      // grand total
    }
}

// ---------------- kernel 3: AP term accumulation ----------------
__global__ void k_ap() {
    int idx = blockIdx.x * blockDim.x + threadIdx.x;
    if (idx >= NBATCH * NB) return;
    int rec = g_records[idx];
    if (!(rec & 0x40000000)) return;
    if (!((rec >> 24) & 1)) return;

    int c = rec & 0xFF;
    int rank = (rec >> 8) & 0xFF;
    int tpc_loc = (rec >> 16) & 0xFF;
    int img = idx / NB;

    int j = g_offv[c * NBATCH + img] + rank + 1;      // 1-based global valid rank
    int tpc = g_offt[c * NBATCH + img] + tpc_loc;     // inclusive cumulative TP

    float pj = (float)tpc / ((float)j + 1e-6f);
    float pprev;
    if (j == 1) {
        pprev = (idx == 0) ? 1.0f : 0.0f;             // only global position 0 sees prepended p=1
    } else {
        pprev = (float)(tpc - 1) / ((float)(j - 1) + 1e-6f);
    }
    float gt = (float)g_gt[c];
    double term = (double)(pj + pprev) * 0.5 / (double)(gt + 1e-6f);
    atomicAdd(&g_ap[c], term);
}

// ---------------- kernel 4: finalize mAP ----------------
__global__ void k_final(float* out) {
    if (threadIdx.x == 0) {
        double s = 0.0; int n = 0;
        for (int c = 0; c < NC; c++) {
            if (g_gt[c] > 0) { s += g_ap[c]; n++; }
        }
        double nh = (n > 0) ? (double)n : 1.0;
        out[0] = (float)(s / nh);
    }
}

// ---------------- launcher ----------------
extern "C" void kernel_launch(void* const* d_in, const int* in_sizes, int n_in,
                              void* d_out, int out_size) {
    const float* tgt = (const float*)d_in[0];
    const float* outp = (const float*)d_in[1];
    float* out = (float*)d_out;

    k_per_image<<<NBATCH, 128>>>(tgt, outp);
    k_scan<<<60, 1024>>>();
    k_ap<<<(NBATCH * NB + 255) / 256, 256>>>();
    k_final<<<1, 32>>>(out);
}